// round 12
// baseline (speedup 1.0000x reference)
#include <cuda_runtime.h>
#include <math.h>

#define BSZ 4096
#define HB  128
#define TD  768
#define NS  16        // K-splits for Gram partials (4096/16 = 256 per split)
#define KCH 256

// block counts inside the fused GEMM kernel
#define NB_GT  (21 * NS)          // 336: upper-tri 6x6 tiles x 16 K-splits
#define NB_M   (6 * NS)           // 96
#define NB_GA  (NS)               // 16
#define NB_SIM 528                // upper-tri 32x32 tiles
#define NB_ALL (NB_GT + NB_M + NB_GA + NB_SIM)

// ---------------- scratch (__device__ globals; no allocation) ----------------
static __device__ __align__(16) float g_ln[BSZ * HB];          // normalized logits
static __device__ __align__(16) float g_tn[BSZ * TD];          // normalized teacher
static __device__ float g_qpart[BSZ];                          // per-row quant partial
static __device__ float g_dpart [32 * BSZ];                    // row-denom partials (tile bx >= t)
static __device__ float g_dpart2[32 * BSZ];                    // col-denom partials (tile by <  t)
static __device__ float g_pr[BSZ];                             // per-row contrastive loss
static __device__ __align__(16) float g_gt[NS * TD * TD];      // T^T T partials
static __device__ __align__(16) float g_m [NS * HB * TD];      // A^T T partials
static __device__ __align__(16) float g_ga[NS * HB * HB];      // A^T A partials
static __device__ float g_fro[3 * 64];                         // frobenius block partials
static __device__ int   g_mmode;                               // mask dtype: 0=u8 1=i32 2=f32

// ---------------- mask dtype detection via guaranteed diagonal ----------------
__global__ __launch_bounds__(256) void k_detect(const void* __restrict__ m)
{
    int t = threadIdx.x;
    size_t idx = (size_t)t * BSZ + t;
    const unsigned char* m8 = (const unsigned char*)m;
    const int*  m32 = (const int*)m;
    const float* mf = (const float*)m;
    int ok8  = (m8 [idx] != 0);
    int ok32 = (m32[idx] != 0);
    int okf  = (mf [idx] != 0.0f);
    int a8  = __syncthreads_and(ok8);
    int a32 = __syncthreads_and(ok32);
    int af  = __syncthreads_and(okf);
    if (t == 0) g_mmode = a32 ? 1 : (a8 ? 0 : (af ? 2 : 1));
}

// ---------------- normalize logits + quantization partial ----------------
__global__ __launch_bounds__(128) void k_norm_logits(const float* __restrict__ logits)
{
    int r = blockIdx.x;
    int t = threadIdx.x;
    float x = logits[(size_t)r * HB + t];
    float ss = x * x;
#pragma unroll
    for (int off = 16; off > 0; off >>= 1) ss += __shfl_down_sync(0xffffffffu, ss, off);
    __shared__ float sw[4];
    if ((t & 31) == 0) sw[t >> 5] = ss;
    __syncthreads();
    float n2 = sw[0] + sw[1] + sw[2] + sw[3];
    float inv = 1.0f / fmaxf(sqrtf(n2), 1e-12f);
    g_ln[(size_t)r * HB + t] = x * inv;

    float q = fabsf(fabsf(x) - 1.0f);
#pragma unroll
    for (int off = 16; off > 0; off >>= 1) q += __shfl_down_sync(0xffffffffu, q, off);
    __shared__ float sq[4];
    if ((t & 31) == 0) sq[t >> 5] = q;
    __syncthreads();
    if (t == 0) g_qpart[r] = sq[0] + sq[1] + sq[2] + sq[3];
}

// ---------------- normalize teacher ----------------
__global__ __launch_bounds__(256) void k_norm_teacher(const float* __restrict__ te)
{
    int r = blockIdx.x;
    int t = threadIdx.x;
    const float* row = te + (size_t)r * TD;
    float x0 = row[t], x1 = row[t + 256], x2 = row[t + 512];
    float ss = x0 * x0 + x1 * x1 + x2 * x2;
#pragma unroll
    for (int off = 16; off > 0; off >>= 1) ss += __shfl_down_sync(0xffffffffu, ss, off);
    __shared__ float sw[8];
    if ((t & 31) == 0) sw[t >> 5] = ss;
    __syncthreads();
    float n2 = sw[0] + sw[1] + sw[2] + sw[3] + sw[4] + sw[5] + sw[6] + sw[7];
    float inv = 1.0f / fmaxf(sqrtf(n2), 1e-12f);
    float* dst = g_tn + (size_t)r * TD;
    dst[t] = x0 * inv; dst[t + 256] = x1 * inv; dst[t + 512] = x2 * inv;
}

// ---------------- Gram tile body: Cpart += A[k,p0:+128]^T B[k,q0:+128] ---------
__device__ __forceinline__ void gram_block(const float* __restrict__ A,
                                           const float* __restrict__ Bm,
                                           int CA, int CB, int p0, int q0, int kBase,
                                           float* __restrict__ Cpart,
                                           float (*As)[132], float (*Bs)[132])
{
    const int tid = threadIdx.x;
    const int tx = tid & 15, ty = tid >> 4;

    float acc[8][8];
#pragma unroll
    for (int i = 0; i < 8; i++)
#pragma unroll
        for (int j = 0; j < 8; j++) acc[i][j] = 0.0f;

    for (int kk = 0; kk < KCH; kk += 32) {
#pragma unroll
        for (int l = 0; l < 4; l++) {
            int idx = tid + l * 256;
            int i  = idx >> 5;
            int c4 = idx & 31;
            *(float4*)&As[i][c4 * 4] =
                *(const float4*)&A [(size_t)(kBase + kk + i) * CA + p0 + c4 * 4];
            *(float4*)&Bs[i][c4 * 4] =
                *(const float4*)&Bm[(size_t)(kBase + kk + i) * CB + q0 + c4 * 4];
        }
        __syncthreads();
#pragma unroll
        for (int k = 0; k < 32; k++) {
            float a[8], b[8];
#pragma unroll
            for (int u = 0; u < 8; u++) a[u] = As[k][ty * 8 + u];
#pragma unroll
            for (int u = 0; u < 8; u++) b[u] = Bs[k][tx * 8 + u];
#pragma unroll
            for (int i = 0; i < 8; i++)
#pragma unroll
                for (int j = 0; j < 8; j++) acc[i][j] = fmaf(a[i], b[j], acc[i][j]);
        }
        __syncthreads();
    }

#pragma unroll
    for (int i = 0; i < 8; i++) {
        int row = p0 + ty * 8 + i;
        float* dst = Cpart + (size_t)row * CB + q0 + tx * 8;
        *(float4*)&dst[0] = make_float4(acc[i][0], acc[i][1], acc[i][2], acc[i][3]);
        *(float4*)&dst[4] = make_float4(acc[i][4], acc[i][5], acc[i][6], acc[i][7]);
    }
}

// ---------------- fused GEMM kernel: 3 Grams + symmetric sim ----------------
__global__ __launch_bounds__(256) void k_mega(const float* __restrict__ hash)
{
    __shared__ float As[32][132];
    __shared__ float Bs[32][132];
    int bid = blockIdx.x;

    if (bid < NB_GT) {
        int z = bid / 21, t = bid % 21;
        int by = 0;
        while (t >= 6 - by) { t -= 6 - by; by++; }
        int bx = by + t;
        gram_block(g_tn, g_tn, TD, TD, by * 128, bx * 128, z * KCH,
                   g_gt + (size_t)z * TD * TD, As, Bs);
        return;
    }
    bid -= NB_GT;
    if (bid < NB_M) {
        int z = bid / 6, bx = bid % 6;
        gram_block(hash, g_tn, HB, TD, 0, bx * 128, z * KCH,
                   g_m + (size_t)z * HB * TD, As, Bs);
        return;
    }
    bid -= NB_M;
    if (bid < NB_GA) {
        int z = bid;
        gram_block(hash, hash, HB, HB, 0, 0, z * KCH,
                   g_ga + (size_t)z * HB * HB, As, Bs);
        return;
    }
    bid -= NB_GA;

    // ---- similarity tile (upper triangle, incl. diagonal) ----
    int t = bid;
    int by = 0;
    while (t >= 32 - by) { t -= 32 - by; by++; }
    int bx = by + t;

    const int tid = threadIdx.x;
    const int tx = tid & 15, ty = tid >> 4;
    const int rowBase = by * 128;
    const int colBase = bx * 128;

    float acc[8][8];
#pragma unroll
    for (int i = 0; i < 8; i++)
#pragma unroll
        for (int j = 0; j < 8; j++) acc[i][j] = 0.0f;

    for (int k0 = 0; k0 < HB; k0 += 32) {
#pragma unroll
        for (int l = 0; l < 4; l++) {
            int idx = tid + l * 256;       // float4 id 0..1023
            int r  = idx >> 3;             // 0..127
            int k4 = idx & 7;              // 0..7
            float4 va = *(const float4*)&g_ln[(size_t)(rowBase + r) * HB + k0 + k4 * 4];
            As[k4 * 4 + 0][r] = va.x; As[k4 * 4 + 1][r] = va.y;
            As[k4 * 4 + 2][r] = va.z; As[k4 * 4 + 3][r] = va.w;
            float4 vb = *(const float4*)&g_ln[(size_t)(colBase + r) * HB + k0 + k4 * 4];
            Bs[k4 * 4 + 0][r] = vb.x; Bs[k4 * 4 + 1][r] = vb.y;
            Bs[k4 * 4 + 2][r] = vb.z; Bs[k4 * 4 + 3][r] = vb.w;
        }
        __syncthreads();
#pragma unroll
        for (int k = 0; k < 32; k++) {
            float a[8], b[8];
#pragma unroll
            for (int u = 0; u < 8; u++) a[u] = As[k][ty * 8 + u];
#pragma unroll
            for (int u = 0; u < 8; u++) b[u] = Bs[k][tx * 8 + u];
#pragma unroll
            for (int i = 0; i < 8; i++)
#pragma unroll
                for (int j = 0; j < 8; j++) acc[i][j] = fmaf(a[i], b[j], acc[i][j]);
        }
        __syncthreads();
    }

    // exp in place (diag elements zeroed so they never contribute)
#pragma unroll
    for (int i = 0; i < 8; i++) {
        int row = rowBase + ty * 8 + i;
#pragma unroll
        for (int j = 0; j < 8; j++) {
            int col = colBase + tx * 8 + j;
            float e = __expf(fmaf(acc[i][j], 5.0f, -5.0f));
            acc[i][j] = (col != row) ? e : 0.0f;
        }
    }

    // row sums -> g_dpart[bx][row]
#pragma unroll
    for (int i = 0; i < 8; i++) {
        float d = acc[i][0] + acc[i][1] + acc[i][2] + acc[i][3]
                + acc[i][4] + acc[i][5] + acc[i][6] + acc[i][7];
#pragma unroll
        for (int off = 8; off > 0; off >>= 1)
            d += __shfl_down_sync(0xffffffffu, d, off, 16);
        if (tx == 0) g_dpart[(size_t)bx * BSZ + rowBase + ty * 8 + i] = d;
    }

    // col sums (off-diagonal tiles only) -> g_dpart2[by][col]
    if (bx > by) {
        float* colbuf = (float*)As;   // reuse 16x132 floats of As
#pragma unroll
        for (int j = 0; j < 8; j++) {
            float cs = acc[0][j] + acc[1][j] + acc[2][j] + acc[3][j]
                     + acc[4][j] + acc[5][j] + acc[6][j] + acc[7][j];
            colbuf[ty * 132 + tx * 8 + j] = cs;
        }
        __syncthreads();
        if (tid < 128) {
            float s = 0.0f;
#pragma unroll
            for (int w = 0; w < 16; w++) s += colbuf[w * 132 + tid];
            g_dpart2[(size_t)by * BSZ + colBase + tid] = s;
        }
    }
}

// ---------------- fused: per-row contrastive + frobenius reductions ----------
__global__ __launch_bounds__(256) void k_rowfro(const void* __restrict__ mask)
{
    int bid = blockIdx.x;
    int t = threadIdx.x;

    if (bid < BSZ) {
        // ---- per-row contrastive ----
        int r = bid;
        int mode = g_mmode;
        int tr = r >> 7;   // row's tile index

        float d = 0.0f;
        if (t < 32)
            d = (t >= tr) ? g_dpart[(size_t)t * BSZ + r]
                          : g_dpart2[(size_t)t * BSZ + r];

        float p = 0.0f, c = 0.0f;
        const float4* a4 = (const float4*)(g_ln + (size_t)r * HB);
        size_t rowoff = (size_t)r * BSZ;
        for (int col = t; col < BSZ; col += 256) {
            bool pos;
            if (mode == 1)      pos = ((const int*)mask)[rowoff + col] != 0;
            else if (mode == 0) pos = ((const unsigned char*)mask)[rowoff + col] != 0;
            else                pos = ((const float*)mask)[rowoff + col] != 0.0f;
            if (pos) {
                const float4* b4 = (const float4*)(g_ln + (size_t)col * HB);
                float s = 0.0f;
#pragma unroll
                for (int k = 0; k < 32; k++) {
                    float4 av = a4[k], bv = b4[k];
                    s += av.x * bv.x + av.y * bv.y + av.z * bv.z + av.w * bv.w;
                }
                p += 5.0f * s;
                c += 1.0f;
            }
        }

        __shared__ float sd[256], sp[256], sc[256];
        sd[t] = d; sp[t] = p; sc[t] = c;
        __syncthreads();
        for (int off = 128; off > 0; off >>= 1) {
            if (t < off) {
                sd[t] += sd[t + off];
                sp[t] += sp[t + off];
                sc[t] += sc[t + off];
            }
            __syncthreads();
        }
        if (t == 0)
            g_pr[r] = logf(sd[0]) + 5.0f - sp[0] / fmaxf(sc[0], 1.0f);
        return;
    }

    // ---- frobenius partial reductions ----
    int fb  = bid - BSZ;            // 0..191
    int tag = fb / 64;
    int sub = fb % 64;
    int CA = (tag == 0) ? TD : HB;
    int CB = (tag == 2) ? HB : TD;
    int sym = (tag == 0);
    const float* Cpart = (tag == 0) ? g_gt : (tag == 1) ? g_m : g_ga;
    size_t E = (size_t)CA * CB;

    float local = 0.0f;
    for (size_t e = (size_t)sub * 256 + t; e < E; e += (size_t)64 * 256) {
        int p = (int)(e / CB), q = (int)(e % CB);
        if (sym && p > q) continue;
        float s = 0.0f;
#pragma unroll
        for (int z = 0; z < NS; z++) s += Cpart[(size_t)z * E + e];
        float w = (sym && p != q) ? 2.0f : 1.0f;
        local += w * s * s;
    }
    __shared__ float sm[256];
    sm[t] = local;
    __syncthreads();
    for (int off = 128; off > 0; off >>= 1) {
        if (t < off) sm[t] += sm[t + off];
        __syncthreads();
    }
    if (t == 0) g_fro[tag * 64 + sub] = sm[0];
}

// ---------------- final combine ----------------
__global__ __launch_bounds__(256) void k_final(float* __restrict__ out)
{
    __shared__ double sm[256];
    __shared__ double res[5];
    int t = threadIdx.x;
    for (int stage = 0; stage < 5; stage++) {
        double a = 0.0;
        if (stage == 0) {
            for (int i = t; i < BSZ; i += 256) a += (double)g_qpart[i];
        } else if (stage == 1) {
            for (int i = t; i < BSZ; i += 256) a += (double)g_pr[i];
        } else {
            if (t < 64) a = (double)g_fro[(stage - 2) * 64 + t];
        }
        sm[t] = a;
        __syncthreads();
        for (int off = 128; off > 0; off >>= 1) {
            if (t < off) sm[t] += sm[t + off];
            __syncthreads();
        }
        if (t == 0) res[stage] = sm[0];
        __syncthreads();
    }
    if (t == 0) {
        double quant_sum = res[0];
        double cont_sum  = res[1];
        double froGT     = res[2];
        double froM      = res[3];
        double froGA     = res[4];
        double loss_cont = cont_sum / (double)BSZ;
        double loss_dist = (froGA / (128.0 * 128.0) - 2.0 * froM / 128.0 + froGT)
                           / ((double)BSZ * (double)BSZ);
        double loss_q    = quant_sum / ((double)BSZ * (double)HB);
        out[0] = (float)(loss_cont + 0.5 * loss_dist + 0.01 * loss_q);
    }
}

// ---------------- launch ----------------
extern "C" void kernel_launch(void* const* d_in, const int* in_sizes, int n_in,
                              void* d_out, int out_size)
{
    (void)in_sizes; (void)n_in; (void)out_size;
    const float* logits   = (const float*)d_in[0];
    const float* hash     = (const float*)d_in[1];
    const float* teacher  = (const float*)d_in[2];
    const void*  mask     = (const void*)d_in[3];
    float* out = (float*)d_out;

    k_detect<<<1, 256>>>(mask);
    k_norm_logits<<<BSZ, 128>>>(logits);
    k_norm_teacher<<<BSZ, 256>>>(teacher);

    k_mega<<<NB_ALL, 256>>>(hash);

    k_rowfro<<<BSZ + 192, 256>>>(mask);

    k_final<<<1, 256>>>(out);
}

// round 16
// speedup vs baseline: 1.6159x; 1.6159x over previous
#include <cuda_runtime.h>
#include <math.h>

#define BSZ 4096
#define HB  128
#define TD  768
#define NS  16        // K-splits for Gram partials (4096/16 = 256 per split)
#define KCH 256

// block counts inside the fused GEMM kernel
#define NB_GT  (21 * NS)          // 336: upper-tri 6x6 tiles x 16 K-splits
#define NB_M   (6 * NS)           // 96
#define NB_GA  (NS)               // 16
#define NB_SIM 528                // upper-tri 32x32 tiles
#define NB_ALL (NB_GT + NB_M + NB_GA + NB_SIM)

// ---------------- scratch (__device__ globals; no allocation) ----------------
static __device__ __align__(16) float g_ln[BSZ * HB];          // normalized logits
static __device__ __align__(16) float g_tn[BSZ * TD];          // normalized teacher
static __device__ float g_qpart[BSZ];                          // per-row quant partial
static __device__ float g_dpart [32 * BSZ];                    // row-side denom partials
static __device__ float g_dpart2[32 * BSZ];                    // col-side denom partials
static __device__ float g_ppart [32 * BSZ];                    // row-side pos-sum partials
static __device__ float g_ppart2[32 * BSZ];                    // col-side pos-sum partials
static __device__ float g_cpart [32 * BSZ];                    // row-side count partials
static __device__ float g_cpart2[32 * BSZ];                    // col-side count partials
static __device__ float g_pr[BSZ];                             // per-row contrastive loss
static __device__ __align__(16) float g_gt[NS * TD * TD];      // T^T T partials
static __device__ __align__(16) float g_m [NS * HB * TD];      // A^T T partials
static __device__ __align__(16) float g_ga[NS * HB * HB];      // A^T A partials
static __device__ float g_fro[3 * 64];                         // frobenius block partials
static __device__ int   g_mmode;                               // mask dtype: 0=u8 1=i32 2=f32

__device__ __forceinline__ bool maskAt(const void* m, int mode, size_t idx)
{
    if (mode == 1) return ((const int*)m)[idx] != 0;
    if (mode == 0) return ((const unsigned char*)m)[idx] != 0;
    return ((const float*)m)[idx] != 0.0f;
}

// ---------------- prep: mask-dtype detect + both norms + quant ----------------
__global__ __launch_bounds__(256) void k_prep(const float* __restrict__ logits,
                                              const float* __restrict__ te,
                                              const void* __restrict__ m)
{
    int r = blockIdx.x;
    int t = threadIdx.x;

    // --- mask dtype detection via guaranteed diagonal (block 0 only) ---
    if (r == 0) {
        size_t idx = (size_t)t * BSZ + t;
        int ok8  = (((const unsigned char*)m)[idx] != 0);
        int ok32 = (((const int*)m)[idx] != 0);
        int okf  = (((const float*)m)[idx] != 0.0f);
        int a8  = __syncthreads_and(ok8);
        int a32 = __syncthreads_and(ok32);
        int af  = __syncthreads_and(okf);
        if (t == 0) g_mmode = a32 ? 1 : (a8 ? 0 : (af ? 2 : 1));
    }

    __shared__ float sw[8];

    // --- teacher norm (768 elems, 256 threads) ---
    {
        const float* row = te + (size_t)r * TD;
        float x0 = row[t], x1 = row[t + 256], x2 = row[t + 512];
        float ss = x0 * x0 + x1 * x1 + x2 * x2;
#pragma unroll
        for (int off = 16; off > 0; off >>= 1) ss += __shfl_down_sync(0xffffffffu, ss, off);
        if ((t & 31) == 0) sw[t >> 5] = ss;
        __syncthreads();
        float n2 = sw[0] + sw[1] + sw[2] + sw[3] + sw[4] + sw[5] + sw[6] + sw[7];
        float inv = 1.0f / fmaxf(sqrtf(n2), 1e-12f);
        float* dst = g_tn + (size_t)r * TD;
        dst[t] = x0 * inv; dst[t + 256] = x1 * inv; dst[t + 512] = x2 * inv;
        __syncthreads();
    }

    // --- logits norm + quant (128 elems; all 256 threads join barriers) ---
    {
        float x = (t < HB) ? logits[(size_t)r * HB + t] : 0.0f;
        float ss = x * x;
#pragma unroll
        for (int off = 16; off > 0; off >>= 1) ss += __shfl_down_sync(0xffffffffu, ss, off);
        if ((t & 31) == 0) sw[t >> 5] = ss;
        __syncthreads();
        float n2 = sw[0] + sw[1] + sw[2] + sw[3] + sw[4] + sw[5] + sw[6] + sw[7];
        float inv = 1.0f / fmaxf(sqrtf(n2), 1e-12f);
        if (t < HB) g_ln[(size_t)r * HB + t] = x * inv;

        float q = (t < HB) ? fabsf(fabsf(x) - 1.0f) : 0.0f;
#pragma unroll
        for (int off = 16; off > 0; off >>= 1) q += __shfl_down_sync(0xffffffffu, q, off);
        __syncthreads();
        if ((t & 31) == 0) sw[t >> 5] = q;
        __syncthreads();
        if (t == 0) g_qpart[r] = sw[0] + sw[1] + sw[2] + sw[3] + sw[4] + sw[5] + sw[6] + sw[7];
    }
}

// ---------------- Gram tile body: Cpart = A[k,p0:+128]^T B[k,q0:+128] ---------
__device__ __forceinline__ void gram_block(const float* __restrict__ A,
                                           const float* __restrict__ Bm,
                                           int CA, int CB, int p0, int q0, int kBase,
                                           float* __restrict__ Cpart,
                                           float (*As)[132], float (*Bs)[132])
{
    const int tid = threadIdx.x;
    const int tx = tid & 15, ty = tid >> 4;

    float acc[8][8];
#pragma unroll
    for (int i = 0; i < 8; i++)
#pragma unroll
        for (int j = 0; j < 8; j++) acc[i][j] = 0.0f;

    for (int kk = 0; kk < KCH; kk += 32) {
#pragma unroll
        for (int l = 0; l < 4; l++) {
            int idx = tid + l * 256;
            int i  = idx >> 5;
            int c4 = idx & 31;
            *(float4*)&As[i][c4 * 4] =
                *(const float4*)&A [(size_t)(kBase + kk + i) * CA + p0 + c4 * 4];
            *(float4*)&Bs[i][c4 * 4] =
                *(const float4*)&Bm[(size_t)(kBase + kk + i) * CB + q0 + c4 * 4];
        }
        __syncthreads();
#pragma unroll
        for (int k = 0; k < 32; k++) {
            float a[8], b[8];
#pragma unroll
            for (int u = 0; u < 8; u++) a[u] = As[k][ty * 8 + u];
#pragma unroll
            for (int u = 0; u < 8; u++) b[u] = Bs[k][tx * 8 + u];
#pragma unroll
            for (int i = 0; i < 8; i++)
#pragma unroll
                for (int j = 0; j < 8; j++) acc[i][j] = fmaf(a[i], b[j], acc[i][j]);
        }
        __syncthreads();
    }

#pragma unroll
    for (int i = 0; i < 8; i++) {
        int row = p0 + ty * 8 + i;
        float* dst = Cpart + (size_t)row * CB + q0 + tx * 8;
        *(float4*)&dst[0] = make_float4(acc[i][0], acc[i][1], acc[i][2], acc[i][3]);
        *(float4*)&dst[4] = make_float4(acc[i][4], acc[i][5], acc[i][6], acc[i][7]);
    }
}

// ---------------- fused GEMM kernel: 3 Grams + symmetric sim + mask ----------
__global__ __launch_bounds__(256, 2) void k_mega(const float* __restrict__ hash,
                                                 const void* __restrict__ mask)
{
    __shared__ float As[32][132];
    __shared__ float Bs[32][132];
    int bid = blockIdx.x;

    if (bid < NB_GT) {
        int z = bid / 21, t = bid % 21;
        int by = 0;
        while (t >= 6 - by) { t -= 6 - by; by++; }
        int bx = by + t;
        gram_block(g_tn, g_tn, TD, TD, by * 128, bx * 128, z * KCH,
                   g_gt + (size_t)z * TD * TD, As, Bs);
        return;
    }
    bid -= NB_GT;
    if (bid < NB_M) {
        int z = bid / 6, bx = bid % 6;
        gram_block(hash, g_tn, HB, TD, 0, bx * 128, z * KCH,
                   g_m + (size_t)z * HB * TD, As, Bs);
        return;
    }
    bid -= NB_M;
    if (bid < NB_GA) {
        int z = bid;
        gram_block(hash, hash, HB, HB, 0, 0, z * KCH,
                   g_ga + (size_t)z * HB * HB, As, Bs);
        return;
    }
    bid -= NB_GA;

    // ---- similarity tile (upper triangle, incl. diagonal) ----
    int t = bid;
    int by = 0;
    while (t >= 32 - by) { t -= 32 - by; by++; }
    int bx = by + t;

    const int tid = threadIdx.x;
    const int tx = tid & 15, ty = tid >> 4;
    const int rowBase = by * 128;
    const int colBase = bx * 128;
    const int mode = g_mmode;

    float acc[8][8];
#pragma unroll
    for (int i = 0; i < 8; i++)
#pragma unroll
        for (int j = 0; j < 8; j++) acc[i][j] = 0.0f;

    for (int k0 = 0; k0 < HB; k0 += 32) {
#pragma unroll
        for (int l = 0; l < 4; l++) {
            int idx = tid + l * 256;       // float4 id 0..1023
            int r  = idx >> 3;             // 0..127
            int k4 = idx & 7;              // 0..7
            float4 va = *(const float4*)&g_ln[(size_t)(rowBase + r) * HB + k0 + k4 * 4];
            As[k4 * 4 + 0][r] = va.x; As[k4 * 4 + 1][r] = va.y;
            As[k4 * 4 + 2][r] = va.z; As[k4 * 4 + 3][r] = va.w;
            float4 vb = *(const float4*)&g_ln[(size_t)(colBase + r) * HB + k0 + k4 * 4];
            Bs[k4 * 4 + 0][r] = vb.x; Bs[k4 * 4 + 1][r] = vb.y;
            Bs[k4 * 4 + 2][r] = vb.z; Bs[k4 * 4 + 3][r] = vb.w;
        }
        __syncthreads();
#pragma unroll
        for (int k = 0; k < 32; k++) {
            float a[8], b[8];
#pragma unroll
            for (int u = 0; u < 8; u++) a[u] = As[k][ty * 8 + u];
#pragma unroll
            for (int u = 0; u < 8; u++) b[u] = Bs[k][tx * 8 + u];
#pragma unroll
            for (int i = 0; i < 8; i++)
#pragma unroll
                for (int j = 0; j < 8; j++) acc[i][j] = fmaf(a[i], b[j], acc[i][j]);
        }
        __syncthreads();
    }

    // ---- row pass: d (exp, no diag), p/c (masked s) -> *part[bx][row] ----
#pragma unroll
    for (int i = 0; i < 8; i++) {
        int row = rowBase + ty * 8 + i;
        size_t moff = (size_t)row * BSZ + colBase + tx * 8;
        float d = 0.0f, p = 0.0f, c = 0.0f;
#pragma unroll
        for (int j = 0; j < 8; j++) {
            int col = colBase + tx * 8 + j;
            float s = acc[i][j] * 5.0f;
            if (col != row) d += __expf(s - 5.0f);
            if (maskAt(mask, mode, moff + j)) { p += s; c += 1.0f; }
        }
#pragma unroll
        for (int off = 8; off > 0; off >>= 1) {
            d += __shfl_down_sync(0xffffffffu, d, off, 16);
            p += __shfl_down_sync(0xffffffffu, p, off, 16);
            c += __shfl_down_sync(0xffffffffu, c, off, 16);
        }
        if (tx == 0) {
            g_dpart[(size_t)bx * BSZ + row] = d;
            g_ppart[(size_t)bx * BSZ + row] = p;
            g_cpart[(size_t)bx * BSZ + row] = c;
        }
    }

    // ---- col pass (off-diagonal only): transposed pairs -> *part2[by][col] ----
    if (bx > by) {
        float* bufD = (float*)As;               // 16*132 floats
        float* bufP = (float*)As + 16 * 132;    // fits in As (32*132)
        float* bufC = (float*)Bs;               // 16*132 floats
#pragma unroll
        for (int j = 0; j < 8; j++) {
            int col = colBase + tx * 8 + j;
            size_t mbase = (size_t)col * BSZ + rowBase + ty * 8;
            float cd = 0.0f, cp = 0.0f, cc = 0.0f;
#pragma unroll
            for (int i = 0; i < 8; i++) {
                float s = acc[i][j] * 5.0f;
                cd += __expf(s - 5.0f);          // row != col guaranteed (bx > by)
                if (maskAt(mask, mode, mbase + i)) { cp += s; cc += 1.0f; }
            }
            bufD[ty * 132 + tx * 8 + j] = cd;
            bufP[ty * 132 + tx * 8 + j] = cp;
            bufC[ty * 132 + tx * 8 + j] = cc;
        }
        __syncthreads();
        if (tid < 128) {
            float sD = 0.0f, sP = 0.0f, sC = 0.0f;
#pragma unroll
            for (int w = 0; w < 16; w++) {
                sD += bufD[w * 132 + tid];
                sP += bufP[w * 132 + tid];
                sC += bufC[w * 132 + tid];
            }
            g_dpart2[(size_t)by * BSZ + colBase + tid] = sD;
            g_ppart2[(size_t)by * BSZ + colBase + tid] = sP;
            g_cpart2[(size_t)by * BSZ + colBase + tid] = sC;
        }
    }
}

// ---------------- combine: per-row contrastive + frobenius reductions --------
__global__ __launch_bounds__(256) void k_combine()
{
    int bid = blockIdx.x;
    int t = threadIdx.x;

    if (bid < 16) {
        // ---- per-row final: one thread per row ----
        int r = bid * 256 + t;
        int tr = r >> 7;
        float d = 0.0f, p = 0.0f, c = 0.0f;
#pragma unroll 4
        for (int j = 0; j < 32; j++) {
            bool up = (j >= tr);
            size_t o = (size_t)j * BSZ + r;
            d += up ? g_dpart[o] : g_dpart2[o];
            p += up ? g_ppart[o] : g_ppart2[o];
            c += up ? g_cpart[o] : g_cpart2[o];
        }
        g_pr[r] = logf(d) + 5.0f - p / fmaxf(c, 1.0f);
        return;
    }

    // ---- frobenius partial reductions ----
    int fb  = bid - 16;             // 0..191
    int tag = fb / 64;
    int sub = fb % 64;
    int CA = (tag == 0) ? TD : HB;
    int CB = (tag == 2) ? HB : TD;
    int sym = (tag == 0);
    const float* Cpart = (tag == 0) ? g_gt : (tag == 1) ? g_m : g_ga;
    size_t E = (size_t)CA * CB;

    float local = 0.0f;
    for (size_t e = (size_t)sub * 256 + t; e < E; e += (size_t)64 * 256) {
        int p = (int)(e / CB), q = (int)(e % CB);
        if (sym && p > q) continue;
        float s = 0.0f;
#pragma unroll
        for (int z = 0; z < NS; z++) s += Cpart[(size_t)z * E + e];
        float w = (sym && p != q) ? 2.0f : 1.0f;
        local += w * s * s;
    }
    __shared__ float sm[256];
    sm[t] = local;
    __syncthreads();
    for (int off = 128; off > 0; off >>= 1) {
        if (t < off) sm[t] += sm[t + off];
        __syncthreads();
    }
    if (t == 0) g_fro[tag * 64 + sub] = sm[0];
}

// ---------------- final combine ----------------
__global__ __launch_bounds__(256) void k_final(float* __restrict__ out)
{
    __shared__ double sm[256];
    __shared__ double res[5];
    int t = threadIdx.x;
    for (int stage = 0; stage < 5; stage++) {
        double a = 0.0;
        if (stage == 0) {
            for (int i = t; i < BSZ; i += 256) a += (double)g_qpart[i];
        } else if (stage == 1) {
            for (int i = t; i < BSZ; i += 256) a += (double)g_pr[i];
        } else {
            if (t < 64) a = (double)g_fro[(stage - 2) * 64 + t];
        }
        sm[t] = a;
        __syncthreads();
        for (int off = 128; off > 0; off >>= 1) {
            if (t < off) sm[t] += sm[t + off];
            __syncthreads();
        }
        if (t == 0) res[stage] = sm[0];
        __syncthreads();
    }
    if (t == 0) {
        double quant_sum = res[0];
        double cont_sum  = res[1];
        double froGT     = res[2];
        double froM      = res[3];
        double froGA     = res[4];
        double loss_cont = cont_sum / (double)BSZ;
        double loss_dist = (froGA / (128.0 * 128.0) - 2.0 * froM / 128.0 + froGT)
                           / ((double)BSZ * (double)BSZ);
        double loss_q    = quant_sum / ((double)BSZ * (double)HB);
        out[0] = (float)(loss_cont + 0.5 * loss_dist + 0.01 * loss_q);
    }
}

// ---------------- launch ----------------
extern "C" void kernel_launch(void* const* d_in, const int* in_sizes, int n_in,
                              void* d_out, int out_size)
{
    (void)in_sizes; (void)n_in; (void)out_size;
    const float* logits   = (const float*)d_in[0];
    const float* hash     = (const float*)d_in[1];
    const float* teacher  = (const float*)d_in[2];
    const void*  mask     = (const void*)d_in[3];
    float* out = (float*)d_out;

    k_prep<<<BSZ, 256>>>(logits, teacher, mask);
    k_mega<<<NB_ALL, 256>>>(hash, mask);
    k_combine<<<16 + 192, 256>>>();
    k_final<<<1, 256>>>(out);
}

// round 17
// speedup vs baseline: 1.8166x; 1.1242x over previous
#include <cuda_runtime.h>
#include <math.h>

#define BSZ 4096
#define HB  128
#define TD  768
#define NS  16        // K-splits for Gram partials (4096/16 = 256 per split)
#define KCH 256

// block counts inside the fused GEMM kernel
#define NB_GT  (21 * NS)          // 336: upper-tri 6x6 tiles x 16 K-splits
#define NB_M   (6 * NS)           // 96
#define NB_GA  (NS)               // 16
#define NB_SIM 528                // upper-tri 32x32 tiles
#define NB_ALL (NB_GT + NB_M + NB_GA + NB_SIM)

#define NB_COMB (16 + 192)        // combine blocks (row-final + fro)

typedef unsigned long long u64;

// ---------------- packed f32x2 helpers (Blackwell) ----------------
__device__ __forceinline__ u64 pack2(float x, float y) {
    u64 r; asm("mov.b64 %0, {%1, %2};" : "=l"(r) : "f"(x), "f"(y)); return r;
}
__device__ __forceinline__ void unpack2(u64 v, float& x, float& y) {
    asm("mov.b64 {%0, %1}, %2;" : "=f"(x), "=f"(y) : "l"(v));
}
__device__ __forceinline__ void ffma2(u64& d, u64 a, u64 b) {
    asm("fma.rn.f32x2 %0, %1, %2, %3;" : "=l"(d) : "l"(a), "l"(b), "l"(d));
}

// ---------------- scratch (__device__ globals; no allocation) ----------------
static __device__ __align__(16) float g_ln[BSZ * HB];          // normalized logits
static __device__ __align__(16) float g_tn[BSZ * TD];          // normalized teacher
static __device__ float g_qpart[BSZ];                          // per-row quant partial
static __device__ float g_dpart [32 * BSZ];                    // row-side denom partials
static __device__ float g_dpart2[32 * BSZ];                    // col-side denom partials
static __device__ float g_ppart [32 * BSZ];                    // row-side pos-sum partials
static __device__ float g_ppart2[32 * BSZ];                    // col-side pos-sum partials
static __device__ float g_cpart [32 * BSZ];                    // row-side count partials
static __device__ float g_cpart2[32 * BSZ];                    // col-side count partials
static __device__ float g_pr[BSZ];                             // per-row contrastive loss
static __device__ __align__(16) float g_gt[NS * TD * TD];      // T^T T partials
static __device__ __align__(16) float g_m [NS * HB * TD];      // A^T T partials
static __device__ __align__(16) float g_ga[NS * HB * HB];      // A^T A partials
static __device__ float g_fro[3 * 64];                         // frobenius block partials
static __device__ int   g_mmode;                               // mask dtype: 0=u8 1=i32 2=f32
static __device__ unsigned int g_ctr;                          // combine completion counter

__device__ __forceinline__ bool maskAt(const void* m, int mode, size_t idx)
{
    if (mode == 1) return ((const int*)m)[idx] != 0;
    if (mode == 0) return ((const unsigned char*)m)[idx] != 0;
    return ((const float*)m)[idx] != 0.0f;
}

// ---------------- prep: detect + norms + quant + counter reset ----------------
__global__ __launch_bounds__(256) void k_prep(const float* __restrict__ logits,
                                              const float* __restrict__ te,
                                              const void* __restrict__ m)
{
    int r = blockIdx.x;
    int t = threadIdx.x;

    if (r == 0) {
        if (t == 0) g_ctr = 0;
        size_t idx = (size_t)t * BSZ + t;
        int ok8  = (((const unsigned char*)m)[idx] != 0);
        int ok32 = (((const int*)m)[idx] != 0);
        int okf  = (((const float*)m)[idx] != 0.0f);
        int a8  = __syncthreads_and(ok8);
        int a32 = __syncthreads_and(ok32);
        int af  = __syncthreads_and(okf);
        if (t == 0) g_mmode = a32 ? 1 : (a8 ? 0 : (af ? 2 : 1));
    }

    __shared__ float sw[8];

    // --- teacher norm (768 elems, 256 threads) ---
    {
        const float* row = te + (size_t)r * TD;
        float x0 = row[t], x1 = row[t + 256], x2 = row[t + 512];
        float ss = x0 * x0 + x1 * x1 + x2 * x2;
#pragma unroll
        for (int off = 16; off > 0; off >>= 1) ss += __shfl_down_sync(0xffffffffu, ss, off);
        if ((t & 31) == 0) sw[t >> 5] = ss;
        __syncthreads();
        float n2 = sw[0] + sw[1] + sw[2] + sw[3] + sw[4] + sw[5] + sw[6] + sw[7];
        float inv = 1.0f / fmaxf(sqrtf(n2), 1e-12f);
        float* dst = g_tn + (size_t)r * TD;
        dst[t] = x0 * inv; dst[t + 256] = x1 * inv; dst[t + 512] = x2 * inv;
        __syncthreads();
    }

    // --- logits norm + quant (128 elems; all 256 threads join barriers) ---
    {
        float x = (t < HB) ? logits[(size_t)r * HB + t] : 0.0f;
        float ss = x * x;
#pragma unroll
        for (int off = 16; off > 0; off >>= 1) ss += __shfl_down_sync(0xffffffffu, ss, off);
        if ((t & 31) == 0) sw[t >> 5] = ss;
        __syncthreads();
        float n2 = sw[0] + sw[1] + sw[2] + sw[3] + sw[4] + sw[5] + sw[6] + sw[7];
        float inv = 1.0f / fmaxf(sqrtf(n2), 1e-12f);
        if (t < HB) g_ln[(size_t)r * HB + t] = x * inv;

        float q = (t < HB) ? fabsf(fabsf(x) - 1.0f) : 0.0f;
#pragma unroll
        for (int off = 16; off > 0; off >>= 1) q += __shfl_down_sync(0xffffffffu, q, off);
        __syncthreads();
        if ((t & 31) == 0) sw[t >> 5] = q;
        __syncthreads();
        if (t == 0) g_qpart[r] = sw[0] + sw[1] + sw[2] + sw[3] + sw[4] + sw[5] + sw[6] + sw[7];
    }
}

// ---------------- packed-f32x2 128x128 tile mainloop ----------------
// acc2[i][jp] holds cols (2jp, 2jp+1) of the 8x8 microtile.
__device__ __forceinline__ void mma_tile_f32x2(u64 (&acc2)[8][4],
                                               float (*As)[132], float (*Bs)[132])
{
    const int tid = threadIdx.x;
    const int tx = tid & 15, ty = tid >> 4;
#pragma unroll
    for (int k = 0; k < 32; k++) {
        float4 a0 = *(const float4*)&As[k][ty * 8];
        float4 a1 = *(const float4*)&As[k][ty * 8 + 4];
        ulonglong2 b0 = *(const ulonglong2*)&Bs[k][tx * 8];
        ulonglong2 b1 = *(const ulonglong2*)&Bs[k][tx * 8 + 4];
        u64 bb0 = b0.x, bb1 = b0.y, bb2 = b1.x, bb3 = b1.y;
        float av[8] = {a0.x, a0.y, a0.z, a0.w, a1.x, a1.y, a1.z, a1.w};
#pragma unroll
        for (int i = 0; i < 8; i++) {
            u64 ad = pack2(av[i], av[i]);
            ffma2(acc2[i][0], ad, bb0);
            ffma2(acc2[i][1], ad, bb1);
            ffma2(acc2[i][2], ad, bb2);
            ffma2(acc2[i][3], ad, bb3);
        }
    }
}

// ---------------- Gram tile body: Cpart = A[k,p0:+128]^T B[k,q0:+128] ---------
__device__ __forceinline__ void gram_block(const float* __restrict__ A,
                                           const float* __restrict__ Bm,
                                           int CA, int CB, int p0, int q0, int kBase,
                                           float* __restrict__ Cpart,
                                           float (*As)[132], float (*Bs)[132])
{
    const int tid = threadIdx.x;
    const int tx = tid & 15, ty = tid >> 4;

    u64 acc2[8][4];
#pragma unroll
    for (int i = 0; i < 8; i++)
#pragma unroll
        for (int j = 0; j < 4; j++) acc2[i][j] = 0ull;

    for (int kk = 0; kk < KCH; kk += 32) {
#pragma unroll
        for (int l = 0; l < 4; l++) {
            int idx = tid + l * 256;
            int i  = idx >> 5;
            int c4 = idx & 31;
            *(float4*)&As[i][c4 * 4] =
                *(const float4*)&A [(size_t)(kBase + kk + i) * CA + p0 + c4 * 4];
            *(float4*)&Bs[i][c4 * 4] =
                *(const float4*)&Bm[(size_t)(kBase + kk + i) * CB + q0 + c4 * 4];
        }
        __syncthreads();
        mma_tile_f32x2(acc2, As, Bs);
        __syncthreads();
    }

#pragma unroll
    for (int i = 0; i < 8; i++) {
        int row = p0 + ty * 8 + i;
        float v[8];
#pragma unroll
        for (int jp = 0; jp < 4; jp++) unpack2(acc2[i][jp], v[2 * jp], v[2 * jp + 1]);
        float* dst = Cpart + (size_t)row * CB + q0 + tx * 8;
        *(float4*)&dst[0] = make_float4(v[0], v[1], v[2], v[3]);
        *(float4*)&dst[4] = make_float4(v[4], v[5], v[6], v[7]);
    }
}

// ---------------- fused GEMM kernel: 3 Grams + symmetric sim + mask ----------
__global__ __launch_bounds__(256, 2) void k_mega(const float* __restrict__ hash,
                                                 const void* __restrict__ mask)
{
    __shared__ float As[32][132];
    __shared__ float Bs[32][132];
    int bid = blockIdx.x;

    if (bid < NB_GT) {
        int z = bid / 21, t = bid % 21;
        int by = 0;
        while (t >= 6 - by) { t -= 6 - by; by++; }
        int bx = by + t;
        gram_block(g_tn, g_tn, TD, TD, by * 128, bx * 128, z * KCH,
                   g_gt + (size_t)z * TD * TD, As, Bs);
        return;
    }
    bid -= NB_GT;
    if (bid < NB_M) {
        int z = bid / 6, bx = bid % 6;
        gram_block(hash, g_tn, HB, TD, 0, bx * 128, z * KCH,
                   g_m + (size_t)z * HB * TD, As, Bs);
        return;
    }
    bid -= NB_M;
    if (bid < NB_GA) {
        int z = bid;
        gram_block(hash, hash, HB, HB, 0, 0, z * KCH,
                   g_ga + (size_t)z * HB * HB, As, Bs);
        return;
    }
    bid -= NB_GA;

    // ---- similarity tile (upper triangle, incl. diagonal) ----
    int t = bid;
    int by = 0;
    while (t >= 32 - by) { t -= 32 - by; by++; }
    int bx = by + t;

    const int tid = threadIdx.x;
    const int tx = tid & 15, ty = tid >> 4;
    const int rowBase = by * 128;
    const int colBase = bx * 128;
    const int mode = g_mmode;

    u64 acc2[8][4];
#pragma unroll
    for (int i = 0; i < 8; i++)
#pragma unroll
        for (int j = 0; j < 4; j++) acc2[i][j] = 0ull;

    for (int k0 = 0; k0 < HB; k0 += 32) {
#pragma unroll
        for (int l = 0; l < 4; l++) {
            int idx = tid + l * 256;       // float4 id 0..1023
            int r  = idx >> 3;             // 0..127
            int k4 = idx & 7;              // 0..7
            float4 va = *(const float4*)&g_ln[(size_t)(rowBase + r) * HB + k0 + k4 * 4];
            As[k4 * 4 + 0][r] = va.x; As[k4 * 4 + 1][r] = va.y;
            As[k4 * 4 + 2][r] = va.z; As[k4 * 4 + 3][r] = va.w;
            float4 vb = *(const float4*)&g_ln[(size_t)(colBase + r) * HB + k0 + k4 * 4];
            Bs[k4 * 4 + 0][r] = vb.x; Bs[k4 * 4 + 1][r] = vb.y;
            Bs[k4 * 4 + 2][r] = vb.z; Bs[k4 * 4 + 3][r] = vb.w;
        }
        __syncthreads();
        mma_tile_f32x2(acc2, As, Bs);
        __syncthreads();
    }

    float acc[8][8];
#pragma unroll
    for (int i = 0; i < 8; i++)
#pragma unroll
        for (int jp = 0; jp < 4; jp++) unpack2(acc2[i][jp], acc[i][2 * jp], acc[i][2 * jp + 1]);

    // ---- row pass: d (exp, no diag), p/c (masked s) -> *part[bx][row] ----
#pragma unroll
    for (int i = 0; i < 8; i++) {
        int row = rowBase + ty * 8 + i;
        size_t moff = (size_t)row * BSZ + colBase + tx * 8;
        float d = 0.0f, p = 0.0f, c = 0.0f;
#pragma unroll
        for (int j = 0; j < 8; j++) {
            int col = colBase + tx * 8 + j;
            float s = acc[i][j] * 5.0f;
            if (col != row) d += __expf(s - 5.0f);
            if (maskAt(mask, mode, moff + j)) { p += s; c += 1.0f; }
        }
#pragma unroll
        for (int off = 8; off > 0; off >>= 1) {
            d += __shfl_down_sync(0xffffffffu, d, off, 16);
            p += __shfl_down_sync(0xffffffffu, p, off, 16);
            c += __shfl_down_sync(0xffffffffu, c, off, 16);
        }
        if (tx == 0) {
            g_dpart[(size_t)bx * BSZ + row] = d;
            g_ppart[(size_t)bx * BSZ + row] = p;
            g_cpart[(size_t)bx * BSZ + row] = c;
        }
    }

    // ---- col pass (off-diagonal only): transposed pairs -> *part2[by][col] ----
    if (bx > by) {
        float* bufD = (float*)As;               // 16*132 floats
        float* bufP = (float*)As + 16 * 132;    // fits in As (32*132)
        float* bufC = (float*)Bs;               // 16*132 floats
#pragma unroll
        for (int j = 0; j < 8; j++) {
            int col = colBase + tx * 8 + j;
            size_t mbase = (size_t)col * BSZ + rowBase + ty * 8;
            float cd = 0.0f, cp = 0.0f, cc = 0.0f;
#pragma unroll
            for (int i = 0; i < 8; i++) {
                float s = acc[i][j] * 5.0f;
                cd += __expf(s - 5.0f);          // row != col guaranteed (bx > by)
                if (maskAt(mask, mode, mbase + i)) { cp += s; cc += 1.0f; }
            }
            bufD[ty * 132 + tx * 8 + j] = cd;
            bufP[ty * 132 + tx * 8 + j] = cp;
            bufC[ty * 132 + tx * 8 + j] = cc;
        }
        __syncthreads();
        if (tid < 128) {
            float sD = 0.0f, sP = 0.0f, sC = 0.0f;
#pragma unroll
            for (int w = 0; w < 16; w++) {
                sD += bufD[w * 132 + tid];
                sP += bufP[w * 132 + tid];
                sC += bufC[w * 132 + tid];
            }
            g_dpart2[(size_t)by * BSZ + colBase + tid] = sD;
            g_ppart2[(size_t)by * BSZ + colBase + tid] = sP;
            g_cpart2[(size_t)by * BSZ + colBase + tid] = sC;
        }
    }
}

// ---------------- combine: row-final + fro reductions + last-block total ------
__global__ __launch_bounds__(256) void k_combine(float* __restrict__ out)
{
    int bid = blockIdx.x;
    int t = threadIdx.x;

    if (bid < 16) {
        // ---- per-row final: one thread per row ----
        int r = bid * 256 + t;
        int tr = r >> 7;
        float d = 0.0f, p = 0.0f, c = 0.0f;
#pragma unroll 4
        for (int j = 0; j < 32; j++) {
            bool up = (j >= tr);
            size_t o = (size_t)j * BSZ + r;
            d += up ? g_dpart[o] : g_dpart2[o];
            p += up ? g_ppart[o] : g_ppart2[o];
            c += up ? g_cpart[o] : g_cpart2[o];
        }
        g_pr[r] = logf(d) + 5.0f - p / fmaxf(c, 1.0f);
    } else {
        // ---- frobenius partial reductions ----
        int fb  = bid - 16;             // 0..191
        int tag = fb / 64;
        int sub = fb % 64;
        int CA = (tag == 0) ? TD : HB;
        int CB = (tag == 2) ? HB : TD;
        int sym = (tag == 0);
        const float* Cpart = (tag == 0) ? g_gt : (tag == 1) ? g_m : g_ga;
        size_t E = (size_t)CA * CB;

        float local = 0.0f;
        for (size_t e = (size_t)sub * 256 + t; e < E; e += (size_t)64 * 256) {
            int p = (int)(e / CB), q = (int)(e % CB);
            if (sym && p > q) continue;
            float s = 0.0f;
#pragma unroll
            for (int z = 0; z < NS; z++) s += Cpart[(size_t)z * E + e];
            float w = (sym && p != q) ? 2.0f : 1.0f;
            local += w * s * s;
        }
        __shared__ float sm[256];
        sm[t] = local;
        __syncthreads();
        for (int off = 128; off > 0; off >>= 1) {
            if (t < off) sm[t] += sm[t + off];
            __syncthreads();
        }
        if (t == 0) g_fro[tag * 64 + sub] = sm[0];
    }

    // ---- last block computes the final weighted sum ----
    __threadfence();
    __shared__ int amLast;
    if (t == 0) amLast = (atomicAdd(&g_ctr, 1u) == NB_COMB - 1);
    __syncthreads();
    if (!amLast) return;

    const double B2   = (double)BSZ * (double)BSZ;
    const double wGT  = 0.5 / B2;
    const double wM   = -(1.0 / 128.0) / B2;
    const double wGA  = (0.5 / 16384.0) / B2;
    const double wPR  = 1.0 / (double)BSZ;
    const double wQ   = 0.01 / ((double)BSZ * (double)HB);

    double local = 0.0;
    for (int i = t; i < BSZ; i += 256) local += (double)g_pr[i] * wPR;
    for (int i = t; i < BSZ; i += 256) local += (double)g_qpart[i] * wQ;
    if (t < 192) {
        int tag = t / 64;
        double w = (tag == 0) ? wGT : (tag == 1) ? wM : wGA;
        local += (double)g_fro[t] * w;
    }

    __shared__ double sd[256];
    sd[t] = local;
    __syncthreads();
    for (int off = 128; off > 0; off >>= 1) {
        if (t < off) sd[t] += sd[t + off];
        __syncthreads();
    }
    if (t == 0) out[0] = (float)sd[0];
}

// ---------------- launch ----------------
extern "C" void kernel_launch(void* const* d_in, const int* in_sizes, int n_in,
                              void* d_out, int out_size)
{
    (void)in_sizes; (void)n_in; (void)out_size;
    const float* logits   = (const float*)d_in[0];
    const float* hash     = (const float*)d_in[1];
    const float* teacher  = (const float*)d_in[2];
    const void*  mask     = (const void*)d_in[3];
    float* out = (float*)d_out;

    k_prep<<<BSZ, 256>>>(logits, teacher, mask);
    k_mega<<<NB_ALL, 256>>>(hash, mask);
    k_combine<<<NB_COMB, 256>>>(out);
}